// round 1
// baseline (speedup 1.0000x reference)
#include <cuda_runtime.h>
#include <math.h>

// Problem constants
#define B_    2
#define S_    2048
#define HID_  2048
#define H_    16
#define KV_   8
#define D_    128
#define GROUPS (H_ / KV_)   // 2

// Scratch (device globals: allocation-free per harness rules)
__device__ float g_q[(size_t)B_ * H_ * S_ * D_];    // [B,H,S,D]
__device__ float g_k[(size_t)B_ * KV_ * S_ * D_];   // [B,KV,S,D]
__device__ float g_v[(size_t)B_ * KV_ * S_ * D_];   // [B,KV,S,D]
__device__ float g_att[(size_t)B_ * S_ * H_ * D_];  // [B,S,H,D] == [4096,2048] row-major

// ---------------------------------------------------------------------------
// SGEMM: C[M,N] = A[M,K] @ B[K,N], 128x128x16 tiles, 256 threads, 8x8 micro.
// mode 0: write C param (plain row-major)
// mode 1: scatter to g_q  layout [B,16,S,128]
// mode 2: scatter to g_k  layout [B, 8,S,128]
// mode 3: scatter to g_v  layout [B, 8,S,128]
// asrc 1: read A from g_att instead of the A param.
// ---------------------------------------------------------------------------
__global__ __launch_bounds__(256, 2)
void sgemm128(const float* __restrict__ A, const float* __restrict__ Bm,
              float* __restrict__ C, int M, int N, int K, int mode, int asrc)
{
    __shared__ float As[16][128];   // transposed: As[k][m]
    __shared__ float Bs[16][128];

    const float* Ap = asrc ? (const float*)g_att : A;

    const int tid = threadIdx.x;
    const int tx  = tid & 15;       // n-dir
    const int ty  = tid >> 4;       // m-dir
    const int m0  = blockIdx.y * 128;
    const int n0  = blockIdx.x * 128;

    float acc[8][8];
    #pragma unroll
    for (int i = 0; i < 8; i++)
        #pragma unroll
        for (int j = 0; j < 8; j++) acc[i][j] = 0.f;

    // initial tile load (k0 = 0)
    #pragma unroll
    for (int u = 0; u < 2; u++) {
        int f  = tid + u * 256;
        int am = f >> 2;            // 0..127
        int ak = (f & 3) * 4;       // 0,4,8,12
        float4 av = *(const float4*)(Ap + (size_t)(m0 + am) * K + ak);
        As[ak + 0][am] = av.x; As[ak + 1][am] = av.y;
        As[ak + 2][am] = av.z; As[ak + 3][am] = av.w;
        int bk = f >> 5;            // 0..15
        int bn = (f & 31) * 4;      // 0..124
        *(float4*)&Bs[bk][bn] = *(const float4*)(Bm + (size_t)bk * N + n0 + bn);
    }
    __syncthreads();

    for (int k0 = 0; k0 < K; k0 += 16) {
        // prefetch next tile to registers
        float4 an[2], bn4[2];
        const bool has = (k0 + 16) < K;
        if (has) {
            #pragma unroll
            for (int u = 0; u < 2; u++) {
                int f  = tid + u * 256;
                int am = f >> 2;
                int ak = (f & 3) * 4;
                an[u]  = *(const float4*)(Ap + (size_t)(m0 + am) * K + (k0 + 16) + ak);
                int bk = f >> 5;
                int bnc = (f & 31) * 4;
                bn4[u] = *(const float4*)(Bm + (size_t)(k0 + 16 + bk) * N + n0 + bnc);
            }
        }
        // compute on current tile
        #pragma unroll
        for (int kk = 0; kk < 16; kk++) {
            float a[8], b[8];
            *(float4*)(a)     = *(const float4*)&As[kk][ty * 8];
            *(float4*)(a + 4) = *(const float4*)&As[kk][ty * 8 + 4];
            *(float4*)(b)     = *(const float4*)&Bs[kk][tx * 8];
            *(float4*)(b + 4) = *(const float4*)&Bs[kk][tx * 8 + 4];
            #pragma unroll
            for (int i = 0; i < 8; i++)
                #pragma unroll
                for (int j = 0; j < 8; j++)
                    acc[i][j] += a[i] * b[j];
        }
        __syncthreads();
        if (has) {
            #pragma unroll
            for (int u = 0; u < 2; u++) {
                int f  = tid + u * 256;
                int am = f >> 2;
                int ak = (f & 3) * 4;
                As[ak + 0][am] = an[u].x; As[ak + 1][am] = an[u].y;
                As[ak + 2][am] = an[u].z; As[ak + 3][am] = an[u].w;
                int bk = f >> 5;
                int bnc = (f & 31) * 4;
                *(float4*)&Bs[bk][bnc] = bn4[u];
            }
        }
        __syncthreads();
    }

    // epilogue
    float* Cq = g_q; float* Ck = g_k; float* Cv = g_v;
    #pragma unroll
    for (int i = 0; i < 8; i++) {
        int m = m0 + ty * 8 + i;
        int b = m >> 11;            // S_ = 2048
        int s = m & 2047;
        #pragma unroll
        for (int j = 0; j < 8; j++) {
            int n = n0 + tx * 8 + j;
            float v = acc[i][j];
            if (mode == 0) {
                C[(size_t)m * N + n] = v;
            } else {
                int hh = n >> 7;    // D_ = 128
                int d  = n & 127;
                if (mode == 1)
                    Cq[(((size_t)(b * H_ + hh) * S_ + s) * D_) + d] = v;
                else if (mode == 2)
                    Ck[(((size_t)(b * KV_ + hh) * S_ + s) * D_) + d] = v;
                else
                    Cv[(((size_t)(b * KV_ + hh) * S_ + s) * D_) + d] = v;
            }
        }
    }
}

// ---------------------------------------------------------------------------
// Per-head RMSNorm (D=128, eps=1e-6) + RoPE, in place on g_q / g_k.
// which 0 -> g_q (16 heads), which 1 -> g_k (8 heads)
// ---------------------------------------------------------------------------
__global__ __launch_bounds__(128)
void rmsrope(int which, const float* __restrict__ w,
             const float* __restrict__ sinp, const float* __restrict__ cosp)
{
    __shared__ float sh[128];
    __shared__ float red[4];

    float* data = which ? g_k : g_q;
    const int nh = which ? KV_ : H_;

    int bid = blockIdx.x;
    int s   = bid % S_;
    int hh  = (bid / S_) % nh;
    int b   = bid / (S_ * nh);

    float* row = data + ((size_t)(b * nh + hh) * S_ + s) * D_;
    int d = threadIdx.x;

    float v  = row[d];
    float sq = v * v;
    #pragma unroll
    for (int o = 16; o; o >>= 1) sq += __shfl_xor_sync(0xffffffffu, sq, o);
    if ((d & 31) == 0) red[d >> 5] = sq;
    __syncthreads();
    float tot = red[0] + red[1] + red[2] + red[3];

    float xn = v * rsqrtf(tot * (1.0f / 128.0f) + 1e-6f) * w[d];
    sh[d] = xn;
    __syncthreads();

    size_t pidx = ((size_t)b * S_ + s) * D_ + d;
    float c  = cosp[pidx];
    float sn = sinp[pidx];
    float other = (d < 64) ? -sh[d + 64] : sh[d - 64];
    row[d] = xn * c + other * sn;
}

// ---------------------------------------------------------------------------
// Causal flash attention, fp32 SIMT. Block = (q-tile 64, head, batch).
// 256 threads = 16(k) x 16(q). Online softmax; P staged through SMEM.
// Reads g_q/g_k/g_v, writes g_att [B,S,H,D].
// ---------------------------------------------------------------------------
#define FLASH_SMEM ((3 * 64 * 128 + 64 * 64) * 4)

extern __shared__ float fsm[];

__global__ __launch_bounds__(256)
void flashattn()
{
    float* Qs = fsm;                  // 64x128
    float* Ks = fsm + 64 * 128;       // 64x128
    float* Vs = Ks  + 64 * 128;       // 64x128
    float* Ps = Vs  + 64 * 128;       // 64x64

    const int tid = threadIdx.x;
    const int tk  = tid & 15;         // k / d direction
    const int tq  = tid >> 4;         // q direction
    const int qt  = blockIdx.x;       // 0..31
    const int h   = blockIdx.y;
    const int b   = blockIdx.z;
    const int kvh = h / GROUPS;
    const int qb  = qt * 64;
    const float scale = 0.08838834764831845f;  // 1/sqrt(128)

    // load Q tile, pre-scaled
    const float* qg = g_q + ((size_t)(b * H_ + h) * S_ + qb) * D_;
    #pragma unroll
    for (int u = 0; u < 8; u++) {
        int idx = tid + u * 256;      // float4 index, 0..2047
        int r = idx >> 5;
        int c = (idx & 31) * 4;
        float4 qv = *(const float4*)(qg + (size_t)r * 128 + c);
        qv.x *= scale; qv.y *= scale; qv.z *= scale; qv.w *= scale;
        *(float4*)&Qs[r * 128 + c] = qv;
    }

    float m_i[4], l_i[4], acc[4][8];
    #pragma unroll
    for (int i = 0; i < 4; i++) {
        m_i[i] = -1e30f; l_i[i] = 0.f;
        #pragma unroll
        for (int j = 0; j < 8; j++) acc[i][j] = 0.f;
    }

    const float* kg = g_k + ((size_t)(b * KV_ + kvh) * S_) * D_;
    const float* vg = g_v + ((size_t)(b * KV_ + kvh) * S_) * D_;

    const int nkt = qt + 1;           // causal: only tiles up to the diagonal
    for (int kt = 0; kt < nkt; kt++) {
        const int kb = kt * 64;
        __syncthreads();              // protect prior-iter Vs/Ps reads + Q-load
        #pragma unroll
        for (int u = 0; u < 8; u++) {
            int idx = tid + u * 256;
            int r = idx >> 5;
            int c = (idx & 31) * 4;
            *(float4*)&Ks[r * 128 + c] = *(const float4*)(kg + (size_t)(kb + r) * 128 + c);
            *(float4*)&Vs[r * 128 + c] = *(const float4*)(vg + (size_t)(kb + r) * 128 + c);
        }
        __syncthreads();

        // S = Q K^T (pre-scaled)
        float sv[4][4];
        #pragma unroll
        for (int i = 0; i < 4; i++)
            #pragma unroll
            for (int j = 0; j < 4; j++) sv[i][j] = 0.f;

        #pragma unroll 4
        for (int kk = 0; kk < 128; kk += 4) {
            float4 qv[4], kv[4];
            #pragma unroll
            for (int i = 0; i < 4; i++) qv[i] = *(const float4*)&Qs[(tq * 4 + i) * 128 + kk];
            #pragma unroll
            for (int j = 0; j < 4; j++) kv[j] = *(const float4*)&Ks[(tk * 4 + j) * 128 + kk];
            #pragma unroll
            for (int i = 0; i < 4; i++)
                #pragma unroll
                for (int j = 0; j < 4; j++)
                    sv[i][j] += qv[i].x * kv[j].x + qv[i].y * kv[j].y
                              + qv[i].z * kv[j].z + qv[i].w * kv[j].w;
        }

        // causal mask (diagonal tile only)
        if (kt == nkt - 1) {
            #pragma unroll
            for (int i = 0; i < 4; i++) {
                int qi = qb + tq * 4 + i;
                #pragma unroll
                for (int j = 0; j < 4; j++) {
                    int ki = kb + tk * 4 + j;
                    if (ki > qi) sv[i][j] = -1e9f;
                }
            }
        }

        // online softmax (row reduce across 16 tk-threads via shfl.xor)
        #pragma unroll
        for (int i = 0; i < 4; i++) {
            float mx = fmaxf(fmaxf(sv[i][0], sv[i][1]), fmaxf(sv[i][2], sv[i][3]));
            #pragma unroll
            for (int o = 1; o < 16; o <<= 1) mx = fmaxf(mx, __shfl_xor_sync(0xffffffffu, mx, o));
            float mnew = fmaxf(m_i[i], mx);
            float corr = __expf(m_i[i] - mnew);
            float rs = 0.f;
            #pragma unroll
            for (int j = 0; j < 4; j++) { float p = __expf(sv[i][j] - mnew); sv[i][j] = p; rs += p; }
            #pragma unroll
            for (int o = 1; o < 16; o <<= 1) rs += __shfl_xor_sync(0xffffffffu, rs, o);
            l_i[i] = l_i[i] * corr + rs;
            m_i[i] = mnew;
            #pragma unroll
            for (int j = 0; j < 8; j++) acc[i][j] *= corr;
            #pragma unroll
            for (int j = 0; j < 4; j++) Ps[(tq * 4 + i) * 64 + tk * 4 + j] = sv[i][j];
        }
        __syncthreads();

        // O += P @ V : thread covers 4 q-rows x 8 d-cols (d = tk*8..)
        #pragma unroll 4
        for (int kj = 0; kj < 64; kj++) {
            float4 v0 = *(const float4*)&Vs[kj * 128 + tk * 8];
            float4 v1 = *(const float4*)&Vs[kj * 128 + tk * 8 + 4];
            #pragma unroll
            for (int i = 0; i < 4; i++) {
                float p = Ps[(tq * 4 + i) * 64 + kj];
                acc[i][0] += p * v0.x; acc[i][1] += p * v0.y;
                acc[i][2] += p * v0.z; acc[i][3] += p * v0.w;
                acc[i][4] += p * v1.x; acc[i][5] += p * v1.y;
                acc[i][6] += p * v1.z; acc[i][7] += p * v1.w;
            }
        }
    }

    // write O / l  -> g_att [B,S,H,D]
    #pragma unroll
    for (int i = 0; i < 4; i++) {
        float inv = 1.f / l_i[i];
        int q = qb + tq * 4 + i;
        float* op = g_att + (((size_t)(b * S_ + q) * H_ + h) * D_) + tk * 8;
        #pragma unroll
        for (int j = 0; j < 8; j++) op[j] = acc[i][j] * inv;
    }
}

// ---------------------------------------------------------------------------
// kernel_launch: QKV gemms -> rmsnorm+rope -> flash attention -> out proj
// Inputs (metadata order): x, sin, cos, attention_mask, Wq, Wk, Wv, Wo, q_norm_w, k_norm_w
// ---------------------------------------------------------------------------
extern "C" void kernel_launch(void* const* d_in, const int* in_sizes, int n_in,
                              void* d_out, int out_size)
{
    const float* x    = (const float*)d_in[0];
    const float* sinp = (const float*)d_in[1];
    const float* cosp = (const float*)d_in[2];
    // d_in[3] = attention_mask (pure causal; applied analytically)
    const float* Wq   = (const float*)d_in[4];
    const float* Wk   = (const float*)d_in[5];
    const float* Wv   = (const float*)d_in[6];
    const float* Wo   = (const float*)d_in[7];
    const float* qw   = (const float*)d_in[8];
    const float* kw   = (const float*)d_in[9];
    float* out = (float*)d_out;

    const int M = B_ * S_;   // 4096

    // QKV projections with fused layout scatter
    sgemm128<<<dim3(HID_ / 128, M / 128), 256>>>(x, Wq, nullptr, M, H_ * D_,  HID_, 1, 0);
    sgemm128<<<dim3((KV_ * D_) / 128, M / 128), 256>>>(x, Wk, nullptr, M, KV_ * D_, HID_, 2, 0);
    sgemm128<<<dim3((KV_ * D_) / 128, M / 128), 256>>>(x, Wv, nullptr, M, KV_ * D_, HID_, 3, 0);

    // RMSNorm + RoPE on q and k
    rmsrope<<<B_ * H_ * S_, 128>>>(0, qw, sinp, cosp);
    rmsrope<<<B_ * KV_ * S_, 128>>>(1, kw, sinp, cosp);

    // causal flash attention
    cudaFuncSetAttribute(flashattn, cudaFuncAttributeMaxDynamicSharedMemorySize, FLASH_SMEM);
    flashattn<<<dim3(S_ / 64, H_, B_), 256, FLASH_SMEM>>>();

    // output projection: g_att [4096,2048] @ Wo [2048,2048] -> out
    sgemm128<<<dim3(HID_ / 128, M / 128), 256>>>(nullptr, Wo, out, M, HID_, H_ * D_, 0, 1);
}

// round 3
// speedup vs baseline: 1.4320x; 1.4320x over previous
#include <cuda_runtime.h>
#include <cstdint>
#include <math.h>

// Problem constants
#define B_    2
#define S_    2048
#define HID_  2048
#define H_    16
#define KV_   8
#define D_    128
#define GROUPS (H_ / KV_)   // 2

// Scratch (device globals: allocation-free per harness rules)
__device__ float g_q[(size_t)B_ * H_ * S_ * D_];    // [B,H,S,D]
__device__ float g_k[(size_t)B_ * KV_ * S_ * D_];   // [B,KV,S,D]
__device__ float g_v[(size_t)B_ * KV_ * S_ * D_];   // [B,KV,S,D]
__device__ float g_att[(size_t)B_ * S_ * H_ * D_];  // [B,S,H,D] == [4096,2048]
// Transposed (K-major) weights
__device__ float g_wqt[(size_t)(H_ * D_) * HID_];
__device__ float g_wkt[(size_t)(KV_ * D_) * HID_];
__device__ float g_wvt[(size_t)(KV_ * D_) * HID_];
__device__ float g_wot[(size_t)HID_ * (H_ * D_)];

// ---------------------------------------------------------------------------
// Portable PTX helpers (no 'a'-target features — harness compiles compute_103)
// ---------------------------------------------------------------------------
__device__ __forceinline__ uint32_t smem_to_u32(const void* smem_ptr) {
    uint32_t addr;
    asm("{ .reg .u64 tmp; cvta.to.shared.u64 tmp, %1; cvt.u32.u64 %0, tmp; }"
        : "=r"(addr) : "l"(smem_ptr));
    return addr;
}

__device__ __forceinline__ void cp_async16(uint32_t s, const void* g) {
    asm volatile("cp.async.cg.shared.global [%0], [%1], 16;" :: "r"(s), "l"(g));
}
#define CP_COMMIT() asm volatile("cp.async.commit_group;" ::: "memory")
#define CP_WAIT1()  asm volatile("cp.async.wait_group 1;"  ::: "memory")

__device__ __forceinline__ float to_tf32(float x) {
    float y;
    asm("cvt.rna.tf32.f32 %0, %1;" : "=f"(y) : "f"(x));
    return y;
}

// m16n8k8 tf32 MMA (HMMA fallback on Blackwell): D += A*B
__device__ __forceinline__ void mma_tf32(float* d, const uint32_t* a, const uint32_t* b) {
    asm volatile(
        "mma.sync.aligned.m16n8k8.row.col.f32.tf32.tf32.f32 "
        "{%0,%1,%2,%3}, {%4,%5,%6,%7}, {%8,%9}, {%0,%1,%2,%3};"
        : "+f"(d[0]), "+f"(d[1]), "+f"(d[2]), "+f"(d[3])
        : "r"(a[0]), "r"(a[1]), "r"(a[2]), "r"(a[3]), "r"(b[0]), "r"(b[1]));
}

// ---------------------------------------------------------------------------
// Weight transpose: Wt[n*K + k] = tf32(W[k*N + n])
// ---------------------------------------------------------------------------
__global__ __launch_bounds__(256)
void transpose_w(const float* __restrict__ W, float* __restrict__ Wt, int K, int N)
{
    __shared__ float t[32][33];
    int k0 = blockIdx.y * 32, n0 = blockIdx.x * 32;
    int tx = threadIdx.x, ty = threadIdx.y;      // 32 x 8
    #pragma unroll
    for (int i = 0; i < 32; i += 8)
        t[ty + i][tx] = to_tf32(W[(size_t)(k0 + ty + i) * N + n0 + tx]);
    __syncthreads();
    #pragma unroll
    for (int i = 0; i < 32; i += 8)
        Wt[(size_t)(n0 + ty + i) * K + k0 + tx] = t[tx][ty + i];
}

// ---------------------------------------------------------------------------
// Tensor-core tf32 GEMM: C[M,N] = A[M,K] @ Bt[N,K]^T
// CTA 128x128, BK=32, 256 thr, 8 warps as 2(m) x 4(n) of 64x32 warp tiles.
// cp.async 2-stage pipeline. Smem row stride 36 floats -> conflict-free frags.
// mode 0: write C; 1/2/3: scatter to g_q/g_k/g_v [B,h,S,128]. asrc 1: A=g_att.
// ---------------------------------------------------------------------------
#define BM 128
#define BN 128
#define BK 32
#define LDT 36                              // padded row stride (floats)
#define TILE_F (128 * LDT)                  // floats per tile
#define STAGE_F (2 * TILE_F)                // A + B per stage
#define GEMM_SMEM (2 * STAGE_F * 4)         // 2 stages, bytes = 73728

__global__ __launch_bounds__(256, 2)
void gemm_mma(const float* __restrict__ A, const float* __restrict__ Bt,
              float* __restrict__ C, int M, int Ndim, int Kdim, int mode, int asrc)
{
    extern __shared__ float sm[];
    const int tid = threadIdx.x;
    const int wid = tid >> 5;
    const int lane = tid & 31;
    const int m0 = blockIdx.y * BM;
    const int n0 = blockIdx.x * BN;
    const int wm = (wid & 1) * 64;          // warp m-offset within CTA tile
    const int wn = (wid >> 1) * 32;         // warp n-offset

    const float* Ap = (asrc ? (const float*)g_att : A) + (size_t)m0 * Kdim;
    const float* Bp = Bt + (size_t)n0 * Kdim;

    const uint32_t sbase = smem_to_u32(sm);

    float acc[4][4][4];
    #pragma unroll
    for (int i = 0; i < 4; i++)
        #pragma unroll
        for (int j = 0; j < 4; j++)
            #pragma unroll
            for (int q = 0; q < 4; q++) acc[i][j][q] = 0.f;

    const int kchunks = Kdim / BK;

    // async tile loader: A tile then B tile into stage s
    auto load_stage = [&](int s, int c) {
        const uint32_t so = sbase + (uint32_t)(s * STAGE_F * 4);
        const float* Ac = Ap + c * BK;
        const float* Bc = Bp + c * BK;
        #pragma unroll
        for (int u = 0; u < 4; u++) {
            int f = tid + u * 256;          // 0..1023
            int r = f >> 3, c4 = f & 7;
            cp_async16(so + (uint32_t)((r * LDT + c4 * 4) * 4),
                       Ac + (size_t)r * Kdim + c4 * 4);
        }
        #pragma unroll
        for (int u = 0; u < 4; u++) {
            int f = tid + u * 256;
            int r = f >> 3, c4 = f & 7;
            cp_async16(so + (uint32_t)((TILE_F + r * LDT + c4 * 4) * 4),
                       Bc + (size_t)r * Kdim + c4 * 4);
        }
    };

    load_stage(0, 0);
    CP_COMMIT();

    const int fr = lane >> 2;               // fragment row 0..7
    const int fc = lane & 3;                // fragment k 0..3

    for (int c = 0; c < kchunks; c++) {
        if (c + 1 < kchunks) load_stage((c + 1) & 1, c + 1);
        CP_COMMIT();
        CP_WAIT1();
        __syncthreads();

        const uint32_t* As = (const uint32_t*)(sm + (size_t)(c & 1) * STAGE_F);
        const uint32_t* Bs = As + TILE_F;

        #pragma unroll
        for (int ks = 0; ks < 4; ks++) {
            const int kk = ks * 8 + fc;
            uint32_t a[4][4], b[4][2];
            #pragma unroll
            for (int mt = 0; mt < 4; mt++) {
                int row = wm + mt * 16 + fr;
                a[mt][0] = As[row * LDT + kk];
                a[mt][1] = As[(row + 8) * LDT + kk];
                a[mt][2] = As[row * LDT + kk + 4];
                a[mt][3] = As[(row + 8) * LDT + kk + 4];
            }
            #pragma unroll
            for (int nt = 0; nt < 4; nt++) {
                int row = wn + nt * 8 + fr;
                b[nt][0] = Bs[row * LDT + kk];
                b[nt][1] = Bs[row * LDT + kk + 4];
            }
            #pragma unroll
            for (int mt = 0; mt < 4; mt++)
                #pragma unroll
                for (int nt = 0; nt < 4; nt++)
                    mma_tf32(acc[mt][nt], a[mt], b[nt]);
        }
        __syncthreads();
    }

    // epilogue: c0 (r, 2c), c1 (r, 2c+1), c2 (r+8, 2c), c3 (r+8, 2c+1)
    const int c2 = fc * 2;
    #pragma unroll
    for (int mt = 0; mt < 4; mt++) {
        #pragma unroll
        for (int half = 0; half < 2; half++) {
            int m = m0 + wm + mt * 16 + fr + half * 8;
            int bb = m >> 11;               // S_ = 2048
            int s = m & 2047;
            #pragma unroll
            for (int nt = 0; nt < 4; nt++) {
                int n = n0 + wn + nt * 8 + c2;
                float2 v = make_float2(acc[mt][nt][half * 2], acc[mt][nt][half * 2 + 1]);
                float* dst;
                if (mode == 0) {
                    dst = C + (size_t)m * Ndim + n;
                } else {
                    int h = n >> 7, d0 = n & 127;
                    if (mode == 1)      dst = g_q + (((size_t)(bb * H_ + h) * S_ + s) * D_) + d0;
                    else if (mode == 2) dst = g_k + (((size_t)(bb * KV_ + h) * S_ + s) * D_) + d0;
                    else                dst = g_v + (((size_t)(bb * KV_ + h) * S_ + s) * D_) + d0;
                }
                *(float2*)dst = v;
            }
        }
    }
}

// ---------------------------------------------------------------------------
// Per-head RMSNorm (D=128, eps=1e-6) + RoPE, in place on g_q / g_k.
// ---------------------------------------------------------------------------
__global__ __launch_bounds__(128)
void rmsrope(int which, const float* __restrict__ w,
             const float* __restrict__ sinp, const float* __restrict__ cosp)
{
    __shared__ float sh[128];
    __shared__ float red[4];

    float* data = which ? g_k : g_q;
    const int nh = which ? KV_ : H_;

    int bid = blockIdx.x;
    int s   = bid % S_;
    int hh  = (bid / S_) % nh;
    int b   = bid / (S_ * nh);

    float* row = data + ((size_t)(b * nh + hh) * S_ + s) * D_;
    int d = threadIdx.x;

    float v  = row[d];
    float sq = v * v;
    #pragma unroll
    for (int o = 16; o; o >>= 1) sq += __shfl_xor_sync(0xffffffffu, sq, o);
    if ((d & 31) == 0) red[d >> 5] = sq;
    __syncthreads();
    float tot = red[0] + red[1] + red[2] + red[3];

    float xn = v * rsqrtf(tot * (1.0f / 128.0f) + 1e-6f) * w[d];
    sh[d] = xn;
    __syncthreads();

    size_t pidx = ((size_t)b * S_ + s) * D_ + d;
    float c  = cosp[pidx];
    float sn = sinp[pidx];
    float other = (d < 64) ? -sh[d + 64] : sh[d - 64];
    row[d] = xn * c + other * sn;
}

// ---------------------------------------------------------------------------
// Causal flash attention, fp32 SIMT (unchanged).
// ---------------------------------------------------------------------------
#define FLASH_SMEM ((3 * 64 * 128 + 64 * 64) * 4)

extern __shared__ float fsm[];

__global__ __launch_bounds__(256)
void flashattn()
{
    float* Qs = fsm;                  // 64x128
    float* Ks = fsm + 64 * 128;       // 64x128
    float* Vs = Ks  + 64 * 128;       // 64x128
    float* Ps = Vs  + 64 * 128;       // 64x64

    const int tid = threadIdx.x;
    const int tk  = tid & 15;
    const int tq  = tid >> 4;
    const int qt  = blockIdx.x;
    const int h   = blockIdx.y;
    const int b   = blockIdx.z;
    const int kvh = h / GROUPS;
    const int qb  = qt * 64;
    const float scale = 0.08838834764831845f;

    const float* qg = g_q + ((size_t)(b * H_ + h) * S_ + qb) * D_;
    #pragma unroll
    for (int u = 0; u < 8; u++) {
        int idx = tid + u * 256;
        int r = idx >> 5;
        int c = (idx & 31) * 4;
        float4 qv = *(const float4*)(qg + (size_t)r * 128 + c);
        qv.x *= scale; qv.y *= scale; qv.z *= scale; qv.w *= scale;
        *(float4*)&Qs[r * 128 + c] = qv;
    }

    float m_i[4], l_i[4], acc[4][8];
    #pragma unroll
    for (int i = 0; i < 4; i++) {
        m_i[i] = -1e30f; l_i[i] = 0.f;
        #pragma unroll
        for (int j = 0; j < 8; j++) acc[i][j] = 0.f;
    }

    const float* kg = g_k + ((size_t)(b * KV_ + kvh) * S_) * D_;
    const float* vg = g_v + ((size_t)(b * KV_ + kvh) * S_) * D_;

    const int nkt = qt + 1;
    for (int kt = 0; kt < nkt; kt++) {
        const int kb = kt * 64;
        __syncthreads();
        #pragma unroll
        for (int u = 0; u < 8; u++) {
            int idx = tid + u * 256;
            int r = idx >> 5;
            int c = (idx & 31) * 4;
            *(float4*)&Ks[r * 128 + c] = *(const float4*)(kg + (size_t)(kb + r) * 128 + c);
            *(float4*)&Vs[r * 128 + c] = *(const float4*)(vg + (size_t)(kb + r) * 128 + c);
        }
        __syncthreads();

        float sv[4][4];
        #pragma unroll
        for (int i = 0; i < 4; i++)
            #pragma unroll
            for (int j = 0; j < 4; j++) sv[i][j] = 0.f;

        #pragma unroll 4
        for (int kk = 0; kk < 128; kk += 4) {
            float4 qv[4], kv[4];
            #pragma unroll
            for (int i = 0; i < 4; i++) qv[i] = *(const float4*)&Qs[(tq * 4 + i) * 128 + kk];
            #pragma unroll
            for (int j = 0; j < 4; j++) kv[j] = *(const float4*)&Ks[(tk * 4 + j) * 128 + kk];
            #pragma unroll
            for (int i = 0; i < 4; i++)
                #pragma unroll
                for (int j = 0; j < 4; j++)
                    sv[i][j] += qv[i].x * kv[j].x + qv[i].y * kv[j].y
                              + qv[i].z * kv[j].z + qv[i].w * kv[j].w;
        }

        if (kt == nkt - 1) {
            #pragma unroll
            for (int i = 0; i < 4; i++) {
                int qi = qb + tq * 4 + i;
                #pragma unroll
                for (int j = 0; j < 4; j++) {
                    int ki = kb + tk * 4 + j;
                    if (ki > qi) sv[i][j] = -1e9f;
                }
            }
        }

        #pragma unroll
        for (int i = 0; i < 4; i++) {
            float mx = fmaxf(fmaxf(sv[i][0], sv[i][1]), fmaxf(sv[i][2], sv[i][3]));
            #pragma unroll
            for (int o = 1; o < 16; o <<= 1) mx = fmaxf(mx, __shfl_xor_sync(0xffffffffu, mx, o));
            float mnew = fmaxf(m_i[i], mx);
            float corr = __expf(m_i[i] - mnew);
            float rs = 0.f;
            #pragma unroll
            for (int j = 0; j < 4; j++) { float p = __expf(sv[i][j] - mnew); sv[i][j] = p; rs += p; }
            #pragma unroll
            for (int o = 1; o < 16; o <<= 1) rs += __shfl_xor_sync(0xffffffffu, rs, o);
            l_i[i] = l_i[i] * corr + rs;
            m_i[i] = mnew;
            #pragma unroll
            for (int j = 0; j < 8; j++) acc[i][j] *= corr;
            #pragma unroll
            for (int j = 0; j < 4; j++) Ps[(tq * 4 + i) * 64 + tk * 4 + j] = sv[i][j];
        }
        __syncthreads();

        #pragma unroll 4
        for (int kj = 0; kj < 64; kj++) {
            float4 v0 = *(const float4*)&Vs[kj * 128 + tk * 8];
            float4 v1 = *(const float4*)&Vs[kj * 128 + tk * 8 + 4];
            #pragma unroll
            for (int i = 0; i < 4; i++) {
                float p = Ps[(tq * 4 + i) * 64 + kj];
                acc[i][0] += p * v0.x; acc[i][1] += p * v0.y;
                acc[i][2] += p * v0.z; acc[i][3] += p * v0.w;
                acc[i][4] += p * v1.x; acc[i][5] += p * v1.y;
                acc[i][6] += p * v1.z; acc[i][7] += p * v1.w;
            }
        }
    }

    #pragma unroll
    for (int i = 0; i < 4; i++) {
        float inv = 1.f / l_i[i];
        int q = qb + tq * 4 + i;
        float* op = g_att + (((size_t)(b * S_ + q) * H_ + h) * D_) + tk * 8;
        #pragma unroll
        for (int j = 0; j < 8; j++) op[j] = acc[i][j] * inv;
    }
}

// ---------------------------------------------------------------------------
// kernel_launch
// Inputs: x, sin, cos, attention_mask, Wq, Wk, Wv, Wo, q_norm_w, k_norm_w
// ---------------------------------------------------------------------------
extern "C" void kernel_launch(void* const* d_in, const int* in_sizes, int n_in,
                              void* d_out, int out_size)
{
    const float* x    = (const float*)d_in[0];
    const float* sinp = (const float*)d_in[1];
    const float* cosp = (const float*)d_in[2];
    const float* Wq   = (const float*)d_in[4];
    const float* Wk   = (const float*)d_in[5];
    const float* Wv   = (const float*)d_in[6];
    const float* Wo   = (const float*)d_in[7];
    const float* qw   = (const float*)d_in[8];
    const float* kw   = (const float*)d_in[9];
    float* out = (float*)d_out;

    const int M = B_ * S_;   // 4096

    static float* wqt = nullptr; static float* wkt = nullptr;
    static float* wvt = nullptr; static float* wot = nullptr;
    if (!wqt) {
        cudaGetSymbolAddress((void**)&wqt, g_wqt);
        cudaGetSymbolAddress((void**)&wkt, g_wkt);
        cudaGetSymbolAddress((void**)&wvt, g_wvt);
        cudaGetSymbolAddress((void**)&wot, g_wot);
    }

    // transpose weights to K-major (tf32-rounded)
    transpose_w<<<dim3(HID_ / 32, HID_ / 32), dim3(32, 8)>>>(Wq, wqt, HID_, H_ * D_);
    transpose_w<<<dim3((KV_ * D_) / 32, HID_ / 32), dim3(32, 8)>>>(Wk, wkt, HID_, KV_ * D_);
    transpose_w<<<dim3((KV_ * D_) / 32, HID_ / 32), dim3(32, 8)>>>(Wv, wvt, HID_, KV_ * D_);
    transpose_w<<<dim3(HID_ / 32, (H_ * D_) / 32), dim3(32, 8)>>>(Wo, wot, H_ * D_, HID_);

    cudaFuncSetAttribute(gemm_mma, cudaFuncAttributeMaxDynamicSharedMemorySize, GEMM_SMEM);

    // QKV projections (mma.sync tf32)
    gemm_mma<<<dim3((H_ * D_) / BN, M / BM), 256, GEMM_SMEM>>>(
        x, wqt, nullptr, M, H_ * D_, HID_, 1, 0);
    gemm_mma<<<dim3((KV_ * D_) / BN, M / BM), 256, GEMM_SMEM>>>(
        x, wkt, nullptr, M, KV_ * D_, HID_, 2, 0);
    gemm_mma<<<dim3((KV_ * D_) / BN, M / BM), 256, GEMM_SMEM>>>(
        x, wvt, nullptr, M, KV_ * D_, HID_, 3, 0);

    // RMSNorm + RoPE
    rmsrope<<<B_ * H_ * S_, 128>>>(0, qw, sinp, cosp);
    rmsrope<<<B_ * KV_ * S_, 128>>>(1, kw, sinp, cosp);

    // causal flash attention (fp32 SIMT)
    cudaFuncSetAttribute(flashattn, cudaFuncAttributeMaxDynamicSharedMemorySize, FLASH_SMEM);
    flashattn<<<dim3(S_ / 64, H_, B_), 256, FLASH_SMEM>>>();

    // output projection
    gemm_mma<<<dim3(HID_ / BN, M / BM), 256, GEMM_SMEM>>>(
        nullptr, wot, out, M, HID_, H_ * D_, 0, 1);
}